// round 15
// baseline (speedup 1.0000x reference)
#include <cuda_runtime.h>
#include <stdint.h>

// Problem constants (fixed-shape problem: 48x48 grid, regular triangulation)
static constexpr int HH   = 48;
static constexpr int WW   = 48;
static constexpr int N_V  = HH * WW;                                          // 2304
static constexpr int N_E  = HH*(WW-1) + (HH-1)*WW + (HH-1)*(WW-1);            // 6721
static constexpr int N_F  = 2*(HH-1)*(WW-1);                                  // 4418
static constexpr int M_S  = N_V + N_E + N_F;                                  // 13443
static constexpr int N1   = N_F + 1;                                          // 4419 dual nodes

// analytic complex constants
static constexpr int A_NH = HH*(WW-1);        // 2256 horizontal edges
static constexpr int A_NV = (HH-1)*WW;        // 2256 vertical edges
static constexpr int TRI_A = (HH-1)*(WW-1);   // 2209

static constexpr int CNT_X      = 53;         // simplex-blocks
static constexpr int CNT_Q      = 8;          // key chunks
static constexpr int PAIR_BLOCKS = 16;        // 8 per dimension
static constexpr int SEGS       = 64;         // serial segments per dimension

typedef unsigned long long u64;

// Global scratch (no allocations allowed)
__device__ float    g_vals[M_S];
__device__ int      g_rank[M_S];
__device__ float    g_sval[M_S];
__device__ int      g_prtR[8*M_S];
__device__ int      g_prtE[8*M_S];
__device__ uint4    g_erec[N_E];
__device__ unsigned g_ex[N_E + 1];     // sorted edge endpoints (u | v<<16) + sentinel
__device__ unsigned g_ew[N_E + 1];     // sorted dual endpoints (c0 | b<<16) + sentinel
__device__ int      g_c3 = 0;          // k_pair finalize barrier counter

// Order-preserving map float -> uint32
__device__ __forceinline__ unsigned int fsort(float x) {
    unsigned int u = __float_as_uint(x);
    return (u & 0x80000000u) ? ~u : (u | 0x80000000u);
}

// software grid barrier (all blocks co-resident)
__device__ __forceinline__ void gbar(int* c, int target) {
    __syncthreads();
    if (threadIdx.x == 0) {
        __threadfence();
        atomicAdd(c, 1);
        while (__ldcg((const int*)c) < target) __nanosleep(64);
    }
    __syncthreads();
}

// analytic edge endpoints (matches _build_complex exactly)
__device__ __forceinline__ void edge_uv(int e, int& u, int& v) {
    if (e < A_NH) {
        int r = e / (WW-1), c = e % (WW-1);
        u = r * WW + c; v = u + 1;
    } else if (e < A_NH + A_NV) {
        int k = e - A_NH;
        int r = k / WW, c = k % WW;
        u = r * WW + c; v = u + WW;
    } else {
        int k = e - A_NH - A_NV;
        int r = k / (WW-1), c = k % (WW-1);
        u = r * WW + c + 1; v = (r + 1) * WW + c;
    }
}

// analytic edge -> triangle cofaces (c0==c1 iff boundary edge)
__device__ __forceinline__ void edge_cof(int e, int& c0, int& c1) {
    if (e < A_NH) {
        int r = e / (WW-1), c = e % (WW-1);
        int tA = r * (WW-1) + c;
        int tB = TRI_A + (r-1) * (WW-1) + c;
        if (r == 0)            { c0 = c1 = tA; }
        else if (r == HH-1)    { c0 = c1 = tB; }
        else                   { c0 = tA; c1 = tB; }
    } else if (e < A_NH + A_NV) {
        int k = e - A_NH;
        int r = k / WW, c = k % WW;
        int tA = r * (WW-1) + c;
        int tB = TRI_A + r * (WW-1) + (c-1);
        if (c == 0)            { c0 = c1 = tA; }
        else if (c == WW-1)    { c0 = c1 = tB; }
        else                   { c0 = tA; c1 = tB; }
    } else {
        int k = e - A_NH - A_NV;
        c0 = k;
        c1 = TRI_A + k;
    }
}

// analytic simplex filtration value (max over vertices), from img directly
__device__ __forceinline__ float simplex_val(int s, const float* __restrict__ img) {
    if (s < N_V) return img[s];
    if (s < N_V + N_E) {
        int u, v;
        edge_uv(s - N_V, u, v);
        return fmaxf(img[u], img[v]);
    }
    int t = s - N_V - N_E;
    if (t < TRI_A) {
        int rr = t / (WW-1), cc = t % (WW-1);
        int b  = rr * WW + cc;
        return fmaxf(img[b], fmaxf(img[b+1], img[b+WW]));       // v00,v01,v10
    }
    int tt = t - TRI_A;
    int rr = tt / (WW-1), cc = tt % (WW-1);
    int b  = rr * WW + cc;
    return fmaxf(img[b+1], fmaxf(img[b+WW], img[b+WW+1]));      // v01,v10,v11
}

// ---------------------------------------------------------------------------
// K_CNT: single-phase partial rank counting, NO grid barriers.
// Block (sb, q): recomputes chunk q's keys analytically into smem, counts how
// many are below each of its 256 own simplices' keys (also analytic).
// sb==0 column also persists g_vals. Zeroes output; resets k_pair's counter.
// ---------------------------------------------------------------------------
static constexpr int QCH = (M_S + CNT_Q - 1) / CNT_Q;   // 1681

__global__ void __launch_bounds__(256)
k_cnt(const float* __restrict__ img, float* __restrict__ out, int out_n)
{
    __shared__ u64 sk[QCH];
    int q = blockIdx.y, sb = blockIdx.x, tid = threadIdx.x;
    int qb = q * QCH;
    int qn = min(QCH, M_S - qb);
    int bflat = q * CNT_X + sb;

    // zero output (one pass over all blocks); init sentinels + barrier counter
    for (int o = bflat * 256 + tid; o < out_n; o += CNT_X * CNT_Q * 256)
        out[o] = 0.0f;
    if (bflat == 0 && tid == 0) { g_ex[N_E] = 0; g_ew[N_E] = 0; g_c3 = 0; }

    // chunk keys (recomputed from img; L1-resident)
    for (int j = tid; j < qn; j += 256) {
        int s = qb + j;
        float v = simplex_val(s, img);
        sk[j] = ((u64)fsort(v) << 32) | (unsigned int)s;
        if (sb == 0) g_vals[s] = v;      // persist values once per simplex
    }
    __syncthreads();

    int s = sb * 256 + tid;
    if (s >= M_S) return;
    float v = simplex_val(s, img);
    u64 my = ((u64)fsort(v) << 32) | (unsigned int)s;

    int jLo = max(0, min(qn, N_V - qb));
    int jHi = max(jLo, min(qn, N_V + N_E - qb));
    int rank = 0, erank = 0;
    int j = 0;
    #pragma unroll 4
    for (; j < jLo; j++) rank += (sk[j] < my);
    #pragma unroll 4
    for (; j < jHi; j++) { bool lt = sk[j] < my; rank += lt; erank += lt; }
    #pragma unroll 4
    for (; j < qn; j++) rank += (sk[j] < my);

    g_prtR[q * M_S + s] = rank;
    g_prtE[q * M_S + s] = erank;
}

// ---------------------------------------------------------------------------
// K_PAIR: grid=16, 512 threads.
//  phase 0: finalize ranks / sval / sorted edge tables (16 blocks) + gbar(16)
//  per block: staged sweep-free CC -> 8 UF snapshots; 8 concurrent serial UF
//  threads over 64ths of the edge list (dying ranks -> smem sdr); block-local
//  epilogue writes this block's diagram rows. No final grid barrier.
// ---------------------------------------------------------------------------
static constexpr int SDR_N = 896;   // >= max block edge range (841)
static constexpr int SMEM_BYTES = 12 * N1 * 4 + SDR_N * 2 + 64;

__device__ __forceinline__ int cut64(int i) { return (i >= SEGS) ? N_E : 105 * i; }

__device__ __forceinline__ int chase32(unsigned* L, int x) {
    int p = (int)L[x];
    while (p != x) { x = p; p = (int)L[x]; }
    return x;
}

// serial find with path halving on u32 packed words [parent:16 | rank:16]
__device__ __forceinline__ unsigned sfind(unsigned* __restrict__ sg, int x,
                                          unsigned w, int& root)
{
    for (;;) {
        int p = (int)(w >> 16);
        if (p == x) { root = x; return w; }
        unsigned wp = sg[p];
        int gp = (int)(wp >> 16);
        if (gp != p) sg[x] = (w & 0xffffu) | ((unsigned)gp << 16);
        x = p; w = wp;
    }
}

// sweep-free parallel CC hooking of edge slab [lo,hi). Safe writes only:
// hooks at observed roots (re-verified until quiet) + ancestor shortcuts.
// Safe 3-barrier changed-flag protocol.
__device__ __forceinline__ void cc_hook(unsigned* lab, const unsigned* __restrict__ earr,
                                        int lo, int hi, int tid, int* s_changed)
{
    for (;;) {
        if (tid == 0) *s_changed = 0;
        __syncthreads();                       // reset visible before hooking
        for (int j = lo + tid; j < hi; j += 512) {
            unsigned x = earr[j];
            int a = (int)(x & 0xffffu), b = (int)(x >> 16);
            int ra = chase32(lab, a);
            int rb = chase32(lab, b);
            atomicMin(&lab[a], (unsigned)ra);  // ancestor-only shortcuts
            atomicMin(&lab[b], (unsigned)rb);
            if (ra != rb) {
                int mn = min(ra, rb), mx = max(ra, rb);
                atomicMin(&lab[mx], (unsigned)mn);   // hook at observed root
                *s_changed = 1;
            }
        }
        __syncthreads();                       // all hooking done
        bool done = (*s_changed == 0);
        __syncthreads();                       // all READ before next reset
        if (done) break;
    }
}

__global__ void __launch_bounds__(512, 1)
k_pair(const float* __restrict__ img, float* __restrict__ out)
{
    extern __shared__ unsigned smu[];
    __shared__ int s_changed;
    int tid  = threadIdx.x;
    int wid  = tid >> 5, lane = tid & 31;
    int b    = blockIdx.x;

    // ---- phase 0: finalize (sum partials; build rank tables + edge tables) ----
    for (int s = b * 512 + tid; s < M_S; s += PAIR_BLOCKS * 512) {
        int rank = 0;
        #pragma unroll
        for (int q = 0; q < 8; q++) rank += g_prtR[q * M_S + s];
        g_rank[s] = rank;
        float myval = g_vals[s];
        g_sval[rank] = myval;
        if (rank == 0)       out[0] = myval;   // essential H0 birth
        if (rank == M_S - 1) out[1] = myval;   // its death = fmax

        if (s >= N_V && s < N_V + N_E) {
            int erank = 0;
            #pragma unroll
            for (int q = 0; q < 8; q++) erank += g_prtE[q * M_S + s];
            int e = s - N_V;
            int u, v, c0, c1;
            edge_uv(e, u, v);
            edge_cof(e, c0, c1);
            uint4 r;
            r.x = (unsigned)u | ((unsigned)v << 16);
            r.y = __float_as_uint(myval);
            r.z = (unsigned)rank;
            r.w = (unsigned)c0 | ((unsigned)c1 << 16);
            g_erec[erank] = r;
            g_ex[erank] = r.x;
            unsigned bb = (c1 == c0) ? (unsigned)N_F : (unsigned)c1;
            g_ew[erank] = (unsigned)c0 | (bb << 16);
        }
    }
    gbar(&g_c3, PAIR_BLOCKS);

    float2* o0 = (float2*)out;
    float2* o1 = o0 + M_S;

    if (b < 8) {
        // ============================ DIM 0 ============================
        unsigned* seg  = smu;                 // [8*N_V]
        unsigned* lab  = seg + 8*N_V;         // [N_V]
        unsigned* rnk  = lab + N_V;           // [N_V]
        unsigned* rkmA = rnk + N_V;           // [N_V]
        unsigned* rkmB = rkmA + N_V;          // [N_V]
        ushort*   sdr  = (ushort*)(rkmB + N_V);  // [SDR_N]
        int base   = b * 8;
        int lo_blk = cut64(base);
        int hi_blk = cut64(base + 8);

        for (int v = tid; v < N_V; v += 512) {
            lab[v]  = (unsigned)v;
            rnk[v]  = (unsigned)g_rank[v];
            rkmA[v] = 0xffffffffu;
        }
        __syncthreads();

        for (int p = 0; p < 8; p++) {
            if (p == 0) {
                if (base > 0)   // bulk-hook prefix [0, cut64(base))
                    cc_hook(lab, g_ex, 0, lo_blk, tid, &s_changed);
            } else {
                cc_hook(lab, g_ex, cut64(base+p-1), cut64(base+p), tid, &s_changed);
            }
            unsigned* rkm = (p & 1) ? rkmB : rkmA;
            unsigned* rkn = (p & 1) ? rkmA : rkmB;
            for (int v = tid; v < N_V; v += 512) {
                int r = chase32(lab, v);
                lab[v] = (unsigned)r;
                atomicMin(&rkm[r], rnk[v]);
            }
            __syncthreads();
            unsigned* sg = seg + p * N_V;
            for (int v = tid; v < N_V; v += 512) {
                sg[v]  = (lab[v] << 16) | (rkm[lab[v]] & 0xffffu);
                rkn[v] = 0xffffffffu;
            }
            __syncthreads();
        }

        // ---- 8 concurrent serial UF threads; dying = LARGER birth rank ----
        if (lane == 0 && wid < 8) {
            unsigned* sg = seg + wid * N_V;
            int lo = cut64(base + wid), hi = cut64(base + wid + 1);
            int lastIdx = -1; unsigned lastW = 0;
            unsigned x = g_ex[lo];
            int u = (int)(x & 0xffffu), v = (int)(x >> 16);
            unsigned wu = sg[u], wv = sg[v];
            for (int j = lo; j < hi; j++) {
                unsigned x2 = g_ex[j + 1];
                int un = (int)(x2 & 0xffffu), vn = (int)(x2 >> 16);
                unsigned wun = sg[un], wvn = sg[vn];
                if (u == lastIdx) wu = lastW;
                if (v == lastIdx) wv = lastW;
                int pu = (int)(wu >> 16), pv = (int)(wv >> 16);
                unsigned wpu = sg[pu], wpv = sg[pv];
                bool fu = (pu == u), fv = (pv == v);
                int ru, rv; unsigned wru, wrv;
                if (__builtin_expect((int)(((!fu) & ((int)(wpu >> 16) != pu)) |
                                           ((!fv) & ((int)(wpv >> 16) != pv))), 0)) {
                    wru = sfind(sg, u, wu, ru);
                    wrv = sfind(sg, v, wv, rv);
                } else {
                    ru = fu ? u : pu;  wru = fu ? wu : wpu;
                    rv = fv ? v : pv;  wrv = fv ? wv : wpv;
                }
                sg[u] = ((unsigned)ru << 16) | (wru & 0xffffu);
                sg[v] = ((unsigned)rv << 16) | (wrv & 0xffffu);
                bool eq = (ru == rv);
                int bu = (int)(wru & 0xffffu), bv = (int)(wrv & 0xffffu);
                bool uy = (bu > bv);
                int y = uy ? ru : rv;
                unsigned wsur = uy ? wrv : wru;
                sdr[j - lo_blk] = eq ? (ushort)0xffffu : (ushort)(uy ? bu : bv);
                sg[y] = wsur;
                lastIdx = y; lastW = wsur;
                u = un; v = vn; wu = wun; wv = wvn;
            }
        }
        __syncthreads();

        // ---- block-local epilogue: dim0 rows for this block's edge range ----
        for (int j = lo_blk + tid; j < hi_blk; j += 512) {
            int d0 = sdr[j - lo_blk];
            if (d0 != 0xffff)
                o0[d0] = make_float2(g_sval[d0], __uint_as_float(g_erec[j].y));
        }
    } else {
        // ==================== DIM 1 (dual, reversed) ====================
        unsigned* seg  = smu;                 // [8*N1]
        unsigned* lab  = seg + 8*N1;          // [N1]
        unsigned* rnk  = lab + N1;            // [N1]
        unsigned* rkmA = rnk + N1;            // [N1]
        unsigned* rkmB = rkmA + N1;           // [N1]
        ushort*   sdr  = (ushort*)(rkmB + N1);   // [SDR_N]
        int base   = (b - 8) * 8;
        int lo_blk = N_E - cut64(base + 8);
        int hi_blk = N_E - cut64(base);

        for (int t = tid; t < N1; t += 512) {
            lab[t]  = (unsigned)t;
            rnk[t]  = (t < N_F) ? (unsigned)g_rank[N_V + N_E + t] : (unsigned)M_S;
            rkmA[t] = 0u;
        }
        __syncthreads();

        for (int p = 0; p < 8; p++) {
            if (p == 0) {
                if (base > 0)   // bulk-hook suffix [N_E-cut64(base), N_E)
                    cc_hook(lab, g_ew, N_E - cut64(base), N_E, tid, &s_changed);
            } else {
                cc_hook(lab, g_ew, N_E - cut64(base+p), N_E - cut64(base+p-1),
                        tid, &s_changed);
            }
            unsigned* rkm = (p & 1) ? rkmB : rkmA;
            unsigned* rkn = (p & 1) ? rkmA : rkmB;
            for (int t = tid; t < N1; t += 512) {
                int r = chase32(lab, t);
                lab[t] = (unsigned)r;
                atomicMax(&rkm[r], rnk[t]);
            }
            __syncthreads();
            unsigned* sg = seg + p * N1;
            for (int t = tid; t < N1; t += 512) {
                sg[t]  = (lab[t] << 16) | (rkm[lab[t]] & 0xffffu);
                rkn[t] = 0u;
            }
            __syncthreads();
        }

        // ---- 8 concurrent serial UF threads; dying = SMALLER max rank ----
        if (lane == 0 && wid < 8) {
            unsigned* sg = seg + wid * N1;
            int q = base + wid;
            int start = N_E - cut64(q) - 1, end = N_E - cut64(q + 1);
            int lastIdx = -1; unsigned lastW = 0;
            unsigned x = g_ew[start];
            int a = (int)(x & 0xffffu), bn_ = (int)(x >> 16);
            unsigned wa = sg[a], wb = sg[bn_];
            for (int j = start; j >= end; j--) {
                int jn = max(j - 1, 0);
                unsigned x2 = g_ew[jn];
                int an = (int)(x2 & 0xffffu), bn = (int)(x2 >> 16);
                unsigned wan = sg[an], wbn = sg[bn];
                if (a == lastIdx)   wa = lastW;
                if (bn_ == lastIdx) wb = lastW;
                int pa = (int)(wa >> 16), pb = (int)(wb >> 16);
                unsigned wpa = sg[pa], wpb = sg[pb];
                bool fa = (pa == a), fb = (pb == bn_);
                int ra, rb; unsigned wra, wrb;
                if (__builtin_expect((int)(((!fa) & ((int)(wpa >> 16) != pa)) |
                                           ((!fb) & ((int)(wpb >> 16) != pb))), 0)) {
                    wra = sfind(sg, a, wa, ra);
                    wrb = sfind(sg, bn_, wb, rb);
                } else {
                    ra = fa ? a : pa;    wra = fa ? wa : wpa;
                    rb = fb ? bn_ : pb;  wrb = fb ? wb : wpb;
                }
                sg[a]   = ((unsigned)ra << 16) | (wra & 0xffffu);
                sg[bn_] = ((unsigned)rb << 16) | (wrb & 0xffffu);
                bool eq = (ra == rb);
                int ba = (int)(wra & 0xffffu), bbr = (int)(wrb & 0xffffu);
                bool ad = (ba < bbr);
                int y = ad ? ra : rb;
                unsigned wsur = ad ? wrb : wra;
                sdr[j - lo_blk] = eq ? (ushort)0xffffu : (ushort)(ad ? ba : bbr);
                sg[y] = wsur;
                lastIdx = y; lastW = wsur;
                a = an; bn_ = bn; wa = wan; wb = wbn;
            }
        }
        __syncthreads();

        // ---- block-local epilogue: dim1 rows for this block's edge range ----
        for (int j = lo_blk + tid; j < hi_blk; j += 512) {
            int d1 = sdr[j - lo_blk];
            if (d1 != 0xffff) {
                uint4 r = g_erec[j];
                o1[(int)r.z] = make_float2(__uint_as_float(r.y), g_sval[d1]);
            }
        }
    }
}

// ---------------------------------------------------------------------------
extern "C" void kernel_launch(void* const* d_in, const int* in_sizes, int n_in,
                              void* d_out, int out_size)
{
    const float* img = (const float*)d_in[0];
    float*       out = (float*)d_out;

    cudaFuncSetAttribute(k_pair, cudaFuncAttributeMaxDynamicSharedMemorySize, SMEM_BYTES);

    k_cnt <<<dim3(CNT_X, CNT_Q), 256>>>(img, out, out_size);
    k_pair<<<PAIR_BLOCKS, 512, SMEM_BYTES>>>(img, out);
}

// round 17
// speedup vs baseline: 1.1283x; 1.1283x over previous
#include <cuda_runtime.h>
#include <stdint.h>

// Problem constants (fixed-shape problem: 48x48 grid, regular triangulation)
static constexpr int HH   = 48;
static constexpr int WW   = 48;
static constexpr int N_V  = HH * WW;                                          // 2304
static constexpr int N_E  = HH*(WW-1) + (HH-1)*WW + (HH-1)*(WW-1);            // 6721
static constexpr int N_F  = 2*(HH-1)*(WW-1);                                  // 4418
static constexpr int M_S  = N_V + N_E + N_F;                                  // 13443
static constexpr int N1   = N_F + 1;                                          // 4419 dual nodes

// analytic complex constants
static constexpr int A_NH = HH*(WW-1);        // 2256 horizontal edges
static constexpr int A_NV = (HH-1)*WW;        // 2256 vertical edges
static constexpr int TRI_A = (HH-1)*(WW-1);   // 2209

static constexpr int CNT_X      = 53;         // simplex-blocks
static constexpr int CNT_Q      = 8;          // key chunks
static constexpr int PAIR_BLOCKS = 16;        // 8 per dimension
static constexpr int SEGS       = 64;         // serial segments per dimension
static constexpr unsigned INV   = 0x3FFFu;    // rank inverter for dim1 (rank <= 13443)

typedef unsigned long long u64;

// Global scratch (no allocations allowed)
__device__ float    g_vals[M_S];
__device__ int      g_rank[M_S];
__device__ float    g_sval[M_S];
__device__ int      g_prtR[8*M_S];
__device__ int      g_prtE[8*M_S];
__device__ uint4    g_erec[N_E];
__device__ unsigned g_ex[N_E + 1];     // sorted edge endpoints (u | v<<16) + sentinel
__device__ unsigned g_ew[N_E + 1];     // sorted dual endpoints (c0 | b<<16) + sentinel
__device__ int      g_c3 = 0;          // k_pair finalize barrier counter

// Order-preserving map float -> uint32
__device__ __forceinline__ unsigned int fsort(float x) {
    unsigned int u = __float_as_uint(x);
    return (u & 0x80000000u) ? ~u : (u | 0x80000000u);
}

// software grid barrier (all blocks co-resident)
__device__ __forceinline__ void gbar(int* c, int target) {
    __syncthreads();
    if (threadIdx.x == 0) {
        __threadfence();
        atomicAdd(c, 1);
        while (__ldcg((const int*)c) < target) __nanosleep(64);
    }
    __syncthreads();
}

// analytic edge endpoints (matches _build_complex exactly)
__device__ __forceinline__ void edge_uv(int e, int& u, int& v) {
    if (e < A_NH) {
        int r = e / (WW-1), c = e % (WW-1);
        u = r * WW + c; v = u + 1;
    } else if (e < A_NH + A_NV) {
        int k = e - A_NH;
        int r = k / WW, c = k % WW;
        u = r * WW + c; v = u + WW;
    } else {
        int k = e - A_NH - A_NV;
        int r = k / (WW-1), c = k % (WW-1);
        u = r * WW + c + 1; v = (r + 1) * WW + c;
    }
}

// analytic edge -> triangle cofaces (c0==c1 iff boundary edge)
__device__ __forceinline__ void edge_cof(int e, int& c0, int& c1) {
    if (e < A_NH) {
        int r = e / (WW-1), c = e % (WW-1);
        int tA = r * (WW-1) + c;
        int tB = TRI_A + (r-1) * (WW-1) + c;
        if (r == 0)            { c0 = c1 = tA; }
        else if (r == HH-1)    { c0 = c1 = tB; }
        else                   { c0 = tA; c1 = tB; }
    } else if (e < A_NH + A_NV) {
        int k = e - A_NH;
        int r = k / WW, c = k % WW;
        int tA = r * (WW-1) + c;
        int tB = TRI_A + r * (WW-1) + (c-1);
        if (c == 0)            { c0 = c1 = tA; }
        else if (c == WW-1)    { c0 = c1 = tB; }
        else                   { c0 = tA; c1 = tB; }
    } else {
        int k = e - A_NH - A_NV;
        c0 = k;
        c1 = TRI_A + k;
    }
}

// analytic simplex filtration value (max over vertices), from img directly
__device__ __forceinline__ float simplex_val(int s, const float* __restrict__ img) {
    if (s < N_V) return img[s];
    if (s < N_V + N_E) {
        int u, v;
        edge_uv(s - N_V, u, v);
        return fmaxf(img[u], img[v]);
    }
    int t = s - N_V - N_E;
    if (t < TRI_A) {
        int rr = t / (WW-1), cc = t % (WW-1);
        int b  = rr * WW + cc;
        return fmaxf(img[b], fmaxf(img[b+1], img[b+WW]));       // v00,v01,v10
    }
    int tt = t - TRI_A;
    int rr = tt / (WW-1), cc = tt % (WW-1);
    int b  = rr * WW + cc;
    return fmaxf(img[b+1], fmaxf(img[b+WW], img[b+WW+1]));      // v01,v10,v11
}

// ---------------------------------------------------------------------------
// K_CNT: single-phase partial rank counting, NO grid barriers.
// Block (sb, q): recomputes chunk q's keys analytically into smem, counts how
// many are below each of its 256 own simplices' keys (also analytic).
// sb==0 column also persists g_vals. Zeroes output; resets k_pair's counter.
// ---------------------------------------------------------------------------
static constexpr int QCH = (M_S + CNT_Q - 1) / CNT_Q;   // 1681

__global__ void __launch_bounds__(256)
k_cnt(const float* __restrict__ img, float* __restrict__ out, int out_n)
{
    __shared__ u64 sk[QCH];
    int q = blockIdx.y, sb = blockIdx.x, tid = threadIdx.x;
    int qb = q * QCH;
    int qn = min(QCH, M_S - qb);
    int bflat = q * CNT_X + sb;

    // zero output (one pass over all blocks); init sentinels + barrier counter
    for (int o = bflat * 256 + tid; o < out_n; o += CNT_X * CNT_Q * 256)
        out[o] = 0.0f;
    if (bflat == 0 && tid == 0) { g_ex[N_E] = 0; g_ew[N_E] = 0; g_c3 = 0; }

    // chunk keys (recomputed from img; L1-resident)
    for (int j = tid; j < qn; j += 256) {
        int s = qb + j;
        float v = simplex_val(s, img);
        sk[j] = ((u64)fsort(v) << 32) | (unsigned int)s;
        if (sb == 0) g_vals[s] = v;      // persist values once per simplex
    }
    __syncthreads();

    int s = sb * 256 + tid;
    if (s >= M_S) return;
    float v = simplex_val(s, img);
    u64 my = ((u64)fsort(v) << 32) | (unsigned int)s;

    int jLo = max(0, min(qn, N_V - qb));
    int jHi = max(jLo, min(qn, N_V + N_E - qb));
    int rank = 0, erank = 0;
    int j = 0;
    #pragma unroll 4
    for (; j < jLo; j++) rank += (sk[j] < my);
    #pragma unroll 4
    for (; j < jHi; j++) { bool lt = sk[j] < my; rank += lt; erank += lt; }
    #pragma unroll 4
    for (; j < qn; j++) rank += (sk[j] < my);

    g_prtR[q * M_S + s] = rank;
    g_prtE[q * M_S + s] = erank;
}

// ---------------------------------------------------------------------------
// K_PAIR: grid=16, 512 threads.
//  phase 0: finalize ranks / sval / sorted edge tables (16 blocks) + gbar(16)
//  per block: staged sweep-free CC with RANK-EMBEDDED labels
//    lab[x] = (birthkey:16 | node:16), birthkey = rank (dim0) or INV-rank
//    (dim1, so atomicMin picks the MAX-rank representative). Lexicographic
//    atomicMin is monotone; hooks at observed roots + ancestor-word shortcuts
//    (R14 safety argument unchanged). At convergence the root IS the birth
//    simplex and its word carries the component birth rank -> ONE fused
//    sweep per stage does compression + snapshot. No rkm arrays.
//  8 concurrent serial UF threads per block over 64ths of the edge list
//  (dying ranks -> smem sdr); block-local epilogue writes diagram rows.
// ---------------------------------------------------------------------------
static constexpr int SDR_N = 896;   // >= max block edge range (841)
static constexpr int SMEM_BYTES = 9 * N1 * 4 + SDR_N * 2 + 64;

__device__ __forceinline__ int cut64(int i) { return (i >= SEGS) ? N_E : 105 * i; }

// chase the node field of rank-embedded words; returns root, w = root's word
__device__ __forceinline__ int chaseW(unsigned* L, int x, unsigned& w) {
    w = L[x];
    int p = (int)(w & 0xffffu);
    while (p != x) { x = p; w = L[x]; p = (int)(w & 0xffffu); }
    return x;
}

// serial find with path halving on u32 packed words [parent:16 | rank:16]
__device__ __forceinline__ unsigned sfind(unsigned* __restrict__ sg, int x,
                                          unsigned w, int& root)
{
    for (;;) {
        int p = (int)(w >> 16);
        if (p == x) { root = x; return w; }
        unsigned wp = sg[p];
        int gp = (int)(wp >> 16);
        if (gp != p) sg[x] = (w & 0xffffu) | ((unsigned)gp << 16);
        x = p; w = wp;
    }
}

// sweep-free parallel CC hooking of edge slab [lo,hi) on rank-embedded words.
// Safe writes only: hooks at observed roots (re-verified until quiet) +
// ancestor-word shortcuts. Safe 3-barrier changed-flag protocol.
__device__ __forceinline__ void cc_hook(unsigned* lab, const unsigned* __restrict__ earr,
                                        int lo, int hi, int tid, int* s_changed)
{
    for (;;) {
        if (tid == 0) *s_changed = 0;
        __syncthreads();                       // reset visible before hooking
        for (int j = lo + tid; j < hi; j += 512) {
            unsigned x = earr[j];
            int a = (int)(x & 0xffffu), b = (int)(x >> 16);
            unsigned wa, wb;
            int ra = chaseW(lab, a, wa);
            int rb = chaseW(lab, b, wb);
            atomicMin(&lab[a], wa);            // ancestor-word shortcuts
            atomicMin(&lab[b], wb);
            if (ra != rb) {
                if (wa < wb) atomicMin(&lab[rb], wa);   // hook at observed root
                else         atomicMin(&lab[ra], wb);
                *s_changed = 1;
            }
        }
        __syncthreads();                       // all hooking done
        bool done = (*s_changed == 0);
        __syncthreads();                       // all READ before next reset
        if (done) break;
    }
}

__global__ void __launch_bounds__(512, 1)
k_pair(const float* __restrict__ img, float* __restrict__ out)
{
    extern __shared__ unsigned smu[];
    __shared__ int s_changed;
    int tid  = threadIdx.x;
    int wid  = tid >> 5, lane = tid & 31;
    int b    = blockIdx.x;

    // ---- phase 0: finalize (sum partials; build rank tables + edge tables) ----
    for (int s = b * 512 + tid; s < M_S; s += PAIR_BLOCKS * 512) {
        int rank = 0;
        #pragma unroll
        for (int q = 0; q < 8; q++) rank += g_prtR[q * M_S + s];
        g_rank[s] = rank;
        float myval = g_vals[s];
        g_sval[rank] = myval;
        if (rank == 0)       out[0] = myval;   // essential H0 birth
        if (rank == M_S - 1) out[1] = myval;   // its death = fmax

        if (s >= N_V && s < N_V + N_E) {
            int erank = 0;
            #pragma unroll
            for (int q = 0; q < 8; q++) erank += g_prtE[q * M_S + s];
            int e = s - N_V;
            int u, v, c0, c1;
            edge_uv(e, u, v);
            edge_cof(e, c0, c1);
            uint4 r;
            r.x = (unsigned)u | ((unsigned)v << 16);
            r.y = __float_as_uint(myval);
            r.z = (unsigned)rank;
            r.w = (unsigned)c0 | ((unsigned)c1 << 16);
            g_erec[erank] = r;
            g_ex[erank] = r.x;
            unsigned bb = (c1 == c0) ? (unsigned)N_F : (unsigned)c1;
            g_ew[erank] = (unsigned)c0 | (bb << 16);
        }
    }
    gbar(&g_c3, PAIR_BLOCKS);

    float2* o0 = (float2*)out;
    float2* o1 = o0 + M_S;

    if (b < 8) {
        // ============================ DIM 0 ============================
        unsigned* seg = smu;                  // [8*N_V] snapshots
        unsigned* lab = seg + 8*N_V;          // [N_V] rank-embedded labels
        ushort*   sdr = (ushort*)(lab + N_V); // [SDR_N]
        int base   = b * 8;
        int lo_blk = cut64(base);
        int hi_blk = cut64(base + 8);

        for (int v = tid; v < N_V; v += 512)
            lab[v] = ((unsigned)g_rank[v] << 16) | (unsigned)v;
        __syncthreads();

        for (int p = 0; p < 8; p++) {
            if (p == 0) {
                if (base > 0)   // bulk-hook prefix [0, cut64(base))
                    cc_hook(lab, g_ex, 0, lo_blk, tid, &s_changed);
            } else {
                cc_hook(lab, g_ex, cut64(base+p-1), cut64(base+p), tid, &s_changed);
            }
            // fused sweep: compress + snapshot [parent:16 | comprank:16]
            unsigned* sg = seg + p * N_V;
            for (int v = tid; v < N_V; v += 512) {
                unsigned w; int r = chaseW(lab, v, w);
                lab[v] = w;                                    // ancestor write
                sg[v]  = ((unsigned)r << 16) | (w >> 16);
            }
            __syncthreads();
        }

        // ---- 8 concurrent serial UF threads; dying = LARGER birth rank ----
        if (lane == 0 && wid < 8) {
            unsigned* sg = seg + wid * N_V;
            int lo = cut64(base + wid), hi = cut64(base + wid + 1);
            int lastIdx = -1; unsigned lastW = 0;
            unsigned x = g_ex[lo];
            int u = (int)(x & 0xffffu), v = (int)(x >> 16);
            unsigned wu = sg[u], wv = sg[v];
            for (int j = lo; j < hi; j++) {
                unsigned x2 = g_ex[j + 1];
                int un = (int)(x2 & 0xffffu), vn = (int)(x2 >> 16);
                unsigned wun = sg[un], wvn = sg[vn];
                if (u == lastIdx) wu = lastW;
                if (v == lastIdx) wv = lastW;
                int pu = (int)(wu >> 16), pv = (int)(wv >> 16);
                unsigned wpu = sg[pu], wpv = sg[pv];
                bool fu = (pu == u), fv = (pv == v);
                int ru, rv; unsigned wru, wrv;
                if (__builtin_expect((int)(((!fu) & ((int)(wpu >> 16) != pu)) |
                                           ((!fv) & ((int)(wpv >> 16) != pv))), 0)) {
                    wru = sfind(sg, u, wu, ru);
                    wrv = sfind(sg, v, wv, rv);
                } else {
                    ru = fu ? u : pu;  wru = fu ? wu : wpu;
                    rv = fv ? v : pv;  wrv = fv ? wv : wpv;
                }
                sg[u] = ((unsigned)ru << 16) | (wru & 0xffffu);
                sg[v] = ((unsigned)rv << 16) | (wrv & 0xffffu);
                bool eq = (ru == rv);
                int bu = (int)(wru & 0xffffu), bv = (int)(wrv & 0xffffu);
                bool uy = (bu > bv);
                int y = uy ? ru : rv;
                unsigned wsur = uy ? wrv : wru;
                sdr[j - lo_blk] = eq ? (ushort)0xffffu : (ushort)(uy ? bu : bv);
                sg[y] = wsur;
                lastIdx = y; lastW = wsur;
                u = un; v = vn; wu = wun; wv = wvn;
            }
        }
        __syncthreads();

        // ---- block-local epilogue: dim0 rows for this block's edge range ----
        for (int j = lo_blk + tid; j < hi_blk; j += 512) {
            int d0 = sdr[j - lo_blk];
            if (d0 != 0xffff)
                o0[d0] = make_float2(g_sval[d0], __uint_as_float(g_erec[j].y));
        }
    } else {
        // ==================== DIM 1 (dual, reversed) ====================
        unsigned* seg = smu;                  // [8*N1]
        unsigned* lab = seg + 8*N1;           // [N1]
        ushort*   sdr = (ushort*)(lab + N1);  // [SDR_N]
        int base   = (b - 8) * 8;
        int lo_blk = N_E - cut64(base + 8);
        int hi_blk = N_E - cut64(base);

        for (int t = tid; t < N1; t += 512) {
            unsigned rk = (t < N_F) ? (unsigned)g_rank[N_V + N_E + t] : (unsigned)M_S;
            lab[t] = ((INV - rk) << 16) | (unsigned)t;   // inverted: min word = MAX rank
        }
        __syncthreads();

        for (int p = 0; p < 8; p++) {
            if (p == 0) {
                if (base > 0)   // bulk-hook suffix [N_E-cut64(base), N_E)
                    cc_hook(lab, g_ew, N_E - cut64(base), N_E, tid, &s_changed);
            } else {
                cc_hook(lab, g_ew, N_E - cut64(base+p), N_E - cut64(base+p-1),
                        tid, &s_changed);
            }
            // fused sweep: compress + snapshot [parent:16 | comp MAX rank:16]
            unsigned* sg = seg + p * N1;
            for (int t = tid; t < N1; t += 512) {
                unsigned w; int r = chaseW(lab, t, w);
                lab[t] = w;
                sg[t]  = ((unsigned)r << 16) | (INV - (w >> 16));
            }
            __syncthreads();
        }

        // ---- 8 concurrent serial UF threads; dying = SMALLER max rank ----
        if (lane == 0 && wid < 8) {
            unsigned* sg = seg + wid * N1;
            int q = base + wid;
            int start = N_E - cut64(q) - 1, end = N_E - cut64(q + 1);
            int lastIdx = -1; unsigned lastW = 0;
            unsigned x = g_ew[start];
            int a = (int)(x & 0xffffu), bn_ = (int)(x >> 16);
            unsigned wa = sg[a], wb = sg[bn_];
            for (int j = start; j >= end; j--) {
                int jn = max(j - 1, 0);
                unsigned x2 = g_ew[jn];
                int an = (int)(x2 & 0xffffu), bn = (int)(x2 >> 16);
                unsigned wan = sg[an], wbn = sg[bn];
                if (a == lastIdx)   wa = lastW;
                if (bn_ == lastIdx) wb = lastW;
                int pa = (int)(wa >> 16), pb = (int)(wb >> 16);
                unsigned wpa = sg[pa], wpb = sg[pb];
                bool fa = (pa == a), fb = (pb == bn_);
                int ra, rb; unsigned wra, wrb;
                if (__builtin_expect((int)(((!fa) & ((int)(wpa >> 16) != pa)) |
                                           ((!fb) & ((int)(wpb >> 16) != pb))), 0)) {
                    wra = sfind(sg, a, wa, ra);
                    wrb = sfind(sg, bn_, wb, rb);
                } else {
                    ra = fa ? a : pa;    wra = fa ? wa : wpa;
                    rb = fb ? bn_ : pb;  wrb = fb ? wb : wpb;
                }
                sg[a]   = ((unsigned)ra << 16) | (wra & 0xffffu);
                sg[bn_] = ((unsigned)rb << 16) | (wrb & 0xffffu);
                bool eq = (ra == rb);
                int ba = (int)(wra & 0xffffu), bbr = (int)(wrb & 0xffffu);
                bool ad = (ba < bbr);
                int y = ad ? ra : rb;
                unsigned wsur = ad ? wrb : wra;
                sdr[j - lo_blk] = eq ? (ushort)0xffffu : (ushort)(ad ? ba : bbr);
                sg[y] = wsur;
                lastIdx = y; lastW = wsur;
                a = an; bn_ = bn; wa = wan; wb = wbn;
            }
        }
        __syncthreads();

        // ---- block-local epilogue: dim1 rows for this block's edge range ----
        for (int j = lo_blk + tid; j < hi_blk; j += 512) {
            int d1 = sdr[j - lo_blk];
            if (d1 != 0xffff) {
                uint4 r = g_erec[j];
                o1[(int)r.z] = make_float2(__uint_as_float(r.y), g_sval[d1]);
            }
        }
    }
}

// ---------------------------------------------------------------------------
extern "C" void kernel_launch(void* const* d_in, const int* in_sizes, int n_in,
                              void* d_out, int out_size)
{
    const float* img = (const float*)d_in[0];
    float*       out = (float*)d_out;

    cudaFuncSetAttribute(k_pair, cudaFuncAttributeMaxDynamicSharedMemorySize, SMEM_BYTES);

    k_cnt <<<dim3(CNT_X, CNT_Q), 256>>>(img, out, out_size);
    k_pair<<<PAIR_BLOCKS, 512, SMEM_BYTES>>>(img, out);
}